// round 13
// baseline (speedup 1.0000x reference)
#include <cuda_runtime.h>
#include <cuda_bf16.h>
#include <cstdint>

#define NN 50000
#define NE 800000
#define SCHUNK 256
#define SBLKS ((NN + SCHUNK - 1) / SCHUNK)   // 196

// ---------------- scratch ----------------
__device__ int   g_is64;
__device__ int   g_src[NE];
__device__ int   g_dst[NE];
__device__ int   g_cnt[NN];
__device__ int   g_fill[NN];
__device__ int   g_bsum[SBLKS];
__device__ int   g_boff[SBLKS];
__device__ int   g_rowstart[NN + 1];
__device__ int   g_csr_src[NE];
__device__ float g_csr_coef[NE];
__device__ float g_dinv[NN];
__device__ float g_dinv2[NN];
__device__ int   g_tick[4];

// fp32 buffers
__device__ float g_h1[NN * 32];     // id 0
__device__ float g_agg1[NN * 32];   // id 1
__device__ float g_h2[NN * 64];     // id 3
__device__ float g_h3[NN * 128];    // id 5

// pre-split bf16 hi/lo activation pairs
__device__ __nv_bfloat16 g_bh2[NN * 32],  g_bl2[NN * 32];    // agg2  (id 2, K=32)
__device__ __nv_bfloat16 g_bh4[NN * 64],  g_bl4[NN * 64];    // agg3  (id 4, K=64)
__device__ __nv_bfloat16 g_bh6[NN * 256], g_bl6[NN * 256];   // m1    (id 6, K=256)
__device__ __nv_bfloat16 g_bh7[NN * 128], g_bl7[NN * 128];   // m2    (id 7, K=128)

// pre-split transposed weights, bf16 hi/lo, layout [F][K]
// slots: 0=W3(64x128) 1=Wf1(128x256) 2=Wf2(256x128) 3=Wf3(128x64) 4=W1(128x32) 5=W2(32x64)
__device__ __nv_bfloat16 g_wt_hi[6][32768];
__device__ __nv_bfloat16 g_wt_lo[6][32768];

__device__ float g_sum1[32],  g_sq1[32];
__device__ float g_sum2[64],  g_sq2[64];
__device__ float g_sum3[128], g_sq3[128];
__device__ float g_scale1[32],  g_shift1[32];
__device__ float g_scale2[64],  g_shift2[64];
__device__ float g_scale3[128], g_shift3[128];

__device__ __forceinline__ float* dev_buf(int id) {
    switch (id) {
        case 0:  return g_h1;
        case 1:  return g_agg1;
        case 3:  return g_h2;
        default: return g_h3;
    }
}
__device__ __forceinline__ __nv_bfloat16* dev_bh(int id) {
    switch (id) {
        case 2:  return g_bh2;
        case 4:  return g_bh4;
        case 6:  return g_bh6;
        default: return g_bh7;
    }
}
__device__ __forceinline__ __nv_bfloat16* dev_bl(int id) {
    switch (id) {
        case 2:  return g_bl2;
        case 4:  return g_bl4;
        case 6:  return g_bl6;
        default: return g_bl7;
    }
}

// ---------------- init (+parallel dtype detect in block 0) ----------------
__global__ void k_init(const int* __restrict__ w) {
    int i = blockIdx.x * blockDim.x + threadIdx.x;
    if (i < NN) { g_cnt[i] = 0; g_fill[i] = 0; }
    if (i < 128) { g_sum3[i] = 0.f; g_sq3[i] = 0.f; }
    if (i < 64)  { g_sum2[i] = 0.f; g_sq2[i] = 0.f; }
    if (i < 32)  { g_sum1[i] = 0.f; g_sq1[i] = 0.f; }
    if (i < 4)   g_tick[i] = 0;
    if (blockIdx.x == 0) {
        __shared__ int ok;
        if (threadIdx.x == 0) ok = 1;
        __syncthreads();
        if (threadIdx.x < 128) {
            int lo = w[2 * threadIdx.x], hi = w[2 * threadIdx.x + 1];
            if (hi != 0 || lo < 0 || lo >= NN) ok = 0;
        }
        __syncthreads();
        if (threadIdx.x == 0) g_is64 = ok;
    }
}

__global__ void k_convert(const int* __restrict__ w) {
    int e = blockIdx.x * blockDim.x + threadIdx.x;
    if (e >= NE) return;
    int s, d;
    if (g_is64) { s = w[2 * e]; d = w[2 * (NE + e)]; }
    else        { s = w[e];     d = w[NE + e]; }
    s = min(max(s, 0), NN - 1);
    d = min(max(d, 0), NN - 1);
    g_src[e] = s;
    g_dst[e] = d;
    atomicAdd(&g_cnt[d], 1);
}

// ---------- scan: partial sums (+ fused scan of partials in last block) ----------
__global__ __launch_bounds__(SCHUNK) void k_partsum() {
    __shared__ int sh[SCHUNK];
    __shared__ int lastflag;
    int idx = blockIdx.x * SCHUNK + threadIdx.x;
    int v = (idx < NN) ? g_cnt[idx] : 0;
    sh[threadIdx.x] = v;
    __syncthreads();
    for (int off = SCHUNK / 2; off > 0; off >>= 1) {
        if (threadIdx.x < off) sh[threadIdx.x] += sh[threadIdx.x + off];
        __syncthreads();
    }
    if (threadIdx.x == 0) g_bsum[blockIdx.x] = sh[0];
    __threadfence();
    __syncthreads();
    if (threadIdx.x == 0)
        lastflag = (atomicAdd(&g_tick[3], 1) == (int)gridDim.x - 1) ? 1 : 0;
    __syncthreads();
    if (lastflag) {
        int t = threadIdx.x;
        int u = (t < SBLKS) ? g_bsum[t] : 0;
        sh[t] = u;
        __syncthreads();
        for (int off = 1; off < SCHUNK; off <<= 1) {
            int w = (t >= off) ? sh[t - off] : 0;
            __syncthreads();
            sh[t] += w;
            __syncthreads();
        }
        if (t < SBLKS) g_boff[t] = sh[t] - u;   // exclusive
    }
}

__global__ __launch_bounds__(SCHUNK) void k_rowstart() {
    __shared__ int sh[SCHUNK];
    int idx = blockIdx.x * SCHUNK + threadIdx.x;
    int c = (idx < NN) ? g_cnt[idx] : 0;
    sh[threadIdx.x] = c;
    __syncthreads();
    for (int off = 1; off < SCHUNK; off <<= 1) {
        int u = (threadIdx.x >= off) ? sh[threadIdx.x - off] : 0;
        __syncthreads();
        sh[threadIdx.x] += u;
        __syncthreads();
    }
    if (idx < NN) {
        int rs = g_boff[blockIdx.x] + sh[threadIdx.x] - c;
        g_rowstart[idx] = rs;
        float r = rsqrtf((float)(c + 1));
        g_dinv[idx]  = r;
        g_dinv2[idx] = r * r;
        if (idx == NN - 1) g_rowstart[NN] = rs + c;
    }
}

__global__ void k_fill() {
    int e = blockIdx.x * blockDim.x + threadIdx.x;
    if (e >= NE) return;
    int s = g_src[e], d = g_dst[e];
    int pos = g_rowstart[d] + atomicAdd(&g_fill[d], 1);
    g_csr_src[pos]  = s;
    g_csr_coef[pos] = g_dinv[s] * g_dinv[d];
}

// ---------------- weight prep (all 6 slots fused): W[K][F] fp32 -> [F][K] bf16 hi/lo ----
__global__ void k_prepw_all(const float* __restrict__ w0, const float* __restrict__ w1,
                            const float* __restrict__ w2, const float* __restrict__ w3,
                            const float* __restrict__ w4, const float* __restrict__ w5) {
    int idx = blockIdx.x * blockDim.x + threadIdx.x;
    if (idx >= 88064) return;
    int slot, base, K;
    const float* W;
    if      (idx < 8192)  { slot = 0; base = 0;     K = 64;  W = w0; }
    else if (idx < 40960) { slot = 1; base = 8192;  K = 128; W = w1; }
    else if (idx < 73728) { slot = 2; base = 40960; K = 256; W = w2; }
    else if (idx < 81920) { slot = 3; base = 73728; K = 128; W = w3; }
    else if (idx < 86016) { slot = 4; base = 81920; K = 128; W = w4; }
    else                  { slot = 5; base = 86016; K = 32;  W = w5; }
    int li = idx - base;
    int sz = (slot == 0 || slot == 3) ? 8192 : (slot == 1 || slot == 2) ? 32768 :
             (slot == 4) ? 4096 : 2048;
    int F = sz / K;
    int f = li / K, k = li % K;
    float v = W[(size_t)k * F + f];
    __nv_bfloat16 h = __float2bfloat16(v);
    __nv_bfloat16 l = __float2bfloat16(v - __bfloat162float(h));
    g_wt_hi[slot][li] = h;
    g_wt_lo[slot][li] = l;
}

// ---------------- HMMA bf16 split GEMM ----------------
#define MMA_BF16(d, a, b)                                                       \
    asm volatile("mma.sync.aligned.m16n8k16.row.col.f32.bf16.bf16.f32 "         \
        "{%0,%1,%2,%3}, {%4,%5,%6,%7}, {%8,%9}, {%0,%1,%2,%3};"                 \
        : "+f"(d[0]), "+f"(d[1]), "+f"(d[2]), "+f"(d[3])                        \
        : "r"(a[0]), "r"(a[1]), "r"(a[2]), "r"(a[3]), "r"(b[0]), "r"(b[1]))

// STATL: 0 none; 2/3 fused BN stats of output. OUTF: fused final 64->10 GEMM.
// APRE: A already split bf16 hi/lo (pure copy load). WBF16: write C as bf16 hi/lo pair.
template <int BN, int EPI, int LAYERA, int STATL, int OUTF = 0, int APRE = 0, int WBF16 = 0>
__global__ __launch_bounds__(2 * (BN / 32) * 32)
void k_gemm_mma(const float* __restrict__ Aext, int aId, int wslot,
                const float* __restrict__ bias,
                const float* __restrict__ bng, const float* __restrict__ bnbe,
                float* __restrict__ Cext, int cId, int nrows, int K, int F) {
    constexpr int BM = 128, WN = BN / 32, THREADS = 2 * WN * 32;
    constexpr int AS = 40;
    constexpr int ASZ = BM * AS, BSZ = BN * AS;
    extern __shared__ __nv_bfloat16 dsm[];
    __shared__ int lastflag;

    const float* A = (!APRE && Aext) ? Aext : (!APRE ? dev_buf(aId) : nullptr);
    const __nv_bfloat16* __restrict__ Ahg = APRE ? dev_bh(aId) : nullptr;
    const __nv_bfloat16* __restrict__ Alg = APRE ? dev_bl(aId) : nullptr;
    float* C = WBF16 ? nullptr : (Cext ? Cext : dev_buf(cId));
    __nv_bfloat16* __restrict__ Chg = WBF16 ? dev_bh(cId) : nullptr;
    __nv_bfloat16* __restrict__ Clg = WBF16 ? dev_bl(cId) : nullptr;
    const __nv_bfloat16* __restrict__ Wh = g_wt_hi[wslot];
    const __nv_bfloat16* __restrict__ Wl = g_wt_lo[wslot];

    int tid = threadIdx.x, wid = tid >> 5, lane = tid & 31;
    int warpM = wid / WN, warpN = wid % WN;
    int grp = lane >> 2, tig = lane & 3;
    int row0 = blockIdx.x * BM, c0 = blockIdx.y * BN;

    float acc[4][4][4];
#pragma unroll
    for (int mt = 0; mt < 4; mt++)
#pragma unroll
        for (int nt = 0; nt < 4; nt++)
#pragma unroll
            for (int q = 0; q < 4; q++) acc[mt][nt][q] = 0.f;

    __nv_bfloat16* Ah = dsm;
    __nv_bfloat16* Al = Ah + ASZ;
    __nv_bfloat16* Bh = Al + ASZ;
    __nv_bfloat16* Bl = Bh + BSZ;

    for (int k0 = 0; k0 < K; k0 += 32) {
        if (APRE) {
            for (int u = tid; u < BM * 8; u += THREADS) {
                int r = u >> 3, q = (u & 7) * 4;
                uint2 vh = make_uint2(0u, 0u), vl = make_uint2(0u, 0u);
                if (row0 + r < nrows) {
                    vh = *reinterpret_cast<const uint2*>(&Ahg[(size_t)(row0 + r) * K + k0 + q]);
                    vl = *reinterpret_cast<const uint2*>(&Alg[(size_t)(row0 + r) * K + k0 + q]);
                }
                *reinterpret_cast<uint2*>(&Ah[r * AS + q]) = vh;
                *reinterpret_cast<uint2*>(&Al[r * AS + q]) = vl;
            }
        } else {
            for (int u = tid; u < BM * 2; u += THREADS) {
                int r = u >> 1, h = (u & 1) * 16;
                float vv[16];
                if (row0 + r < nrows) {
#pragma unroll
                    for (int q = 0; q < 4; q++) {
                        float4 v = *reinterpret_cast<const float4*>(
                            &A[(size_t)(row0 + r) * K + k0 + h + q * 4]);
                        vv[q * 4] = v.x; vv[q * 4 + 1] = v.y; vv[q * 4 + 2] = v.z; vv[q * 4 + 3] = v.w;
                    }
                } else {
#pragma unroll
                    for (int q = 0; q < 16; q++) vv[q] = 0.f;
                }
                if (LAYERA == 3) {
#pragma unroll
                    for (int q = 0; q < 16; q++)
                        vv[q] = fmaxf(fmaf(vv[q], g_scale3[k0 + h + q], g_shift3[k0 + h + q]), 0.f);
                }
#pragma unroll
                for (int q = 0; q < 16; q += 2) {
                    __nv_bfloat162 hp = __float22bfloat162_rn(make_float2(vv[q], vv[q + 1]));
                    float l0 = vv[q]     - __bfloat162float(hp.x);
                    float l1 = vv[q + 1] - __bfloat162float(hp.y);
                    __nv_bfloat162 lp = __float22bfloat162_rn(make_float2(l0, l1));
                    *reinterpret_cast<uint32_t*>(&Ah[r * AS + h + q]) = *reinterpret_cast<uint32_t*>(&hp);
                    *reinterpret_cast<uint32_t*>(&Al[r * AS + h + q]) = *reinterpret_cast<uint32_t*>(&lp);
                }
            }
        }
        for (int u = tid; u < BN * 8; u += THREADS) {
            int n = u >> 3, q = (u & 7) * 4;
            uint2 vh = *reinterpret_cast<const uint2*>(&Wh[(size_t)(c0 + n) * K + k0 + q]);
            uint2 vl = *reinterpret_cast<const uint2*>(&Wl[(size_t)(c0 + n) * K + k0 + q]);
            *reinterpret_cast<uint2*>(&Bh[n * AS + q]) = vh;
            *reinterpret_cast<uint2*>(&Bl[n * AS + q]) = vl;
        }
        __syncthreads();

#pragma unroll
        for (int ks = 0; ks < 32; ks += 16) {
            uint32_t bhf[4][2], blf[4][2];
#pragma unroll
            for (int nt = 0; nt < 4; nt++) {
                int n = warpN * 32 + nt * 8 + grp;
                bhf[nt][0] = *reinterpret_cast<const uint32_t*>(&Bh[n * AS + ks + tig * 2]);
                bhf[nt][1] = *reinterpret_cast<const uint32_t*>(&Bh[n * AS + ks + tig * 2 + 8]);
                blf[nt][0] = *reinterpret_cast<const uint32_t*>(&Bl[n * AS + ks + tig * 2]);
                blf[nt][1] = *reinterpret_cast<const uint32_t*>(&Bl[n * AS + ks + tig * 2 + 8]);
            }
#pragma unroll
            for (int mt = 0; mt < 4; mt++) {
                int r0 = warpM * 64 + mt * 16 + grp;
                uint32_t ahf[4], alf[4];
                ahf[0] = *reinterpret_cast<const uint32_t*>(&Ah[r0 * AS + ks + tig * 2]);
                ahf[1] = *reinterpret_cast<const uint32_t*>(&Ah[(r0 + 8) * AS + ks + tig * 2]);
                ahf[2] = *reinterpret_cast<const uint32_t*>(&Ah[r0 * AS + ks + tig * 2 + 8]);
                ahf[3] = *reinterpret_cast<const uint32_t*>(&Ah[(r0 + 8) * AS + ks + tig * 2 + 8]);
                alf[0] = *reinterpret_cast<const uint32_t*>(&Al[r0 * AS + ks + tig * 2]);
                alf[1] = *reinterpret_cast<const uint32_t*>(&Al[(r0 + 8) * AS + ks + tig * 2]);
                alf[2] = *reinterpret_cast<const uint32_t*>(&Al[r0 * AS + ks + tig * 2 + 8]);
                alf[3] = *reinterpret_cast<const uint32_t*>(&Al[(r0 + 8) * AS + ks + tig * 2 + 8]);
#pragma unroll
                for (int nt = 0; nt < 4; nt++) {
                    MMA_BF16(acc[mt][nt], ahf, bhf[nt]);
                    MMA_BF16(acc[mt][nt], ahf, blf[nt]);
                    MMA_BF16(acc[mt][nt], alf, bhf[nt]);
                }
            }
        }
        __syncthreads();
    }

    // ---- epilogue ----
    float* stage = reinterpret_cast<float*>(dsm);   // OUTF staging (stride 65)
    float ls[4][2], lq[4][2];
    if (STATL) {
#pragma unroll
        for (int nt = 0; nt < 4; nt++) { ls[nt][0] = ls[nt][1] = lq[nt][0] = lq[nt][1] = 0.f; }
    }
#pragma unroll
    for (int mt = 0; mt < 4; mt++) {
#pragma unroll
        for (int nt = 0; nt < 4; nt++) {
            int rl = warpM * 64 + mt * 16 + grp;
            int row = row0 + rl;
            int col = c0 + warpN * 32 + nt * 8 + tig * 2;
            float2 v0 = make_float2(acc[mt][nt][0], acc[mt][nt][1]);
            float2 v1 = make_float2(acc[mt][nt][2], acc[mt][nt][3]);
            if (EPI == 2) {
                float b0 = bias[col], b1 = bias[col + 1];
                v0.x = fmaxf(v0.x + b0, 0.f); v0.y = fmaxf(v0.y + b1, 0.f);
                v1.x = fmaxf(v1.x + b0, 0.f); v1.y = fmaxf(v1.y + b1, 0.f);
            }
            if (STATL) {
                ls[nt][0] += v0.x + v1.x;
                ls[nt][1] += v0.y + v1.y;
                lq[nt][0] += v0.x * v0.x + v1.x * v1.x;
                lq[nt][1] += v0.y * v0.y + v1.y * v1.y;
            }
            if (OUTF) {
                stage[rl * 65 + col]       = v0.x;
                stage[rl * 65 + col + 1]   = v0.y;
                stage[(rl + 8) * 65 + col]     = v1.x;
                stage[(rl + 8) * 65 + col + 1] = v1.y;
            } else if (WBF16) {
                __nv_bfloat162 h0 = __float22bfloat162_rn(v0);
                __nv_bfloat162 l0 = __float22bfloat162_rn(
                    make_float2(v0.x - __bfloat162float(h0.x), v0.y - __bfloat162float(h0.y)));
                __nv_bfloat162 h1 = __float22bfloat162_rn(v1);
                __nv_bfloat162 l1 = __float22bfloat162_rn(
                    make_float2(v1.x - __bfloat162float(h1.x), v1.y - __bfloat162float(h1.y)));
                if (row < nrows) {
                    *reinterpret_cast<uint32_t*>(&Chg[(size_t)row * F + col]) = *reinterpret_cast<uint32_t*>(&h0);
                    *reinterpret_cast<uint32_t*>(&Clg[(size_t)row * F + col]) = *reinterpret_cast<uint32_t*>(&l0);
                }
                if (row + 8 < nrows) {
                    *reinterpret_cast<uint32_t*>(&Chg[(size_t)(row + 8) * F + col]) = *reinterpret_cast<uint32_t*>(&h1);
                    *reinterpret_cast<uint32_t*>(&Clg[(size_t)(row + 8) * F + col]) = *reinterpret_cast<uint32_t*>(&l1);
                }
            } else {
                if (row < nrows)
                    *reinterpret_cast<float2*>(&C[(size_t)row * F + col]) = v0;
                if (row + 8 < nrows)
                    *reinterpret_cast<float2*>(&C[(size_t)(row + 8) * F + col]) = v1;
            }
        }
    }

    if (OUTF) {   // fused 64->10 fp32 GEMM: out = stage @ W4 + b4  (W4 in bng, b4 in bnbe)
        float* w4s = stage + 128 * 65;   // 640 floats
        for (int i = tid; i < 640; i += THREADS) w4s[i] = bng[i];
        __syncthreads();
        int row = row0 + tid;
        if (tid < 128 && row < nrows) {
            float o[10];
#pragma unroll
            for (int c = 0; c < 10; c++) o[c] = bnbe[c];
            for (int k = 0; k < 64; k++) {
                float a = stage[tid * 65 + k];
#pragma unroll
                for (int c = 0; c < 10; c++) o[c] = fmaf(a, w4s[k * 10 + c], o[c]);
            }
#pragma unroll
            for (int c = 0; c < 10; c++) Cext[(size_t)row * 10 + c] = o[c];
        }
    }

    if (STATL) {
        float* sum = (STATL == 2) ? g_sum2 : g_sum3;
        float* sq  = (STATL == 2) ? g_sq2  : g_sq3;
        float* scale = (STATL == 2) ? g_scale2 : g_scale3;
        float* shift = (STATL == 2) ? g_shift2 : g_shift3;
#pragma unroll
        for (int nt = 0; nt < 4; nt++) {
#pragma unroll
            for (int c = 0; c < 2; c++) {
                float s = ls[nt][c], q = lq[nt][c];
#pragma unroll
                for (int off = 4; off < 32; off <<= 1) {
                    s += __shfl_xor_sync(0xFFFFFFFFu, s, off);
                    q += __shfl_xor_sync(0xFFFFFFFFu, q, off);
                }
                if (lane < 4) {
                    int col = c0 + warpN * 32 + nt * 8 + lane * 2 + c;
                    atomicAdd(&sum[col], s);
                    atomicAdd(&sq[col], q);
                }
            }
        }
        __threadfence();
        __syncthreads();
        if (tid == 0)
            lastflag = (atomicAdd(&g_tick[STATL - 1], 1) ==
                        (int)(gridDim.x * gridDim.y) - 1) ? 1 : 0;
        __syncthreads();
        if (lastflag && tid < F) {
            float mean = sum[tid] * (1.0f / NN);
            float var  = sq[tid] * (1.0f / NN) - mean * mean;
            float scv  = bng[tid] * rsqrtf(var + 1e-5f);
            scale[tid] = scv;
            shift[tid] = bnbe[tid] - mean * scv;
        }
    }
}

constexpr int mma_smem(int BN) { return (2 * 128 * 40 + 2 * BN * 40) * 2; }
constexpr int mma_smem_outf()  { return (128 * 65 + 640) * 4; }

// ---------------- CSR gather ----------------
// STAT=1: fused BN1 stats (F=32). OUTB=1: write bf16 hi/lo pair instead of fp32.
template <int F, int LAYER, int STAT, int OUTB>
__launch_bounds__(256)
__global__ void k_gather(int hId, int aggId,
                         const float* __restrict__ bng, const float* __restrict__ bnbe) {
    const float* __restrict__ H = dev_buf(hId);
    float* __restrict__ AGG = OUTB ? nullptr : dev_buf(aggId);
    __nv_bfloat16* __restrict__ AGGh = OUTB ? dev_bh(aggId) : nullptr;
    __nv_bfloat16* __restrict__ AGGl = OUTB ? dev_bl(aggId) : nullptr;
    constexpr int V = F / 32;
    __shared__ float ssum[8 * 32], ssq[8 * 32];
    __shared__ int lastflag;
    int wid = threadIdx.x >> 5;
    int node = blockIdx.x * 8 + wid;
    int lane = threadIdx.x & 31;
    int col = lane * V;
    bool valid = node < NN;

    float sc[V], sh[V];
    if (LAYER > 0) {
        const float* scale = (LAYER == 1) ? g_scale1 : g_scale2;
        const float* shift = (LAYER == 1) ? g_shift1 : g_shift2;
#pragma unroll
        for (int v = 0; v < V; v++) { sc[v] = scale[col + v]; sh[v] = shift[col + v]; }
    }

    float acc[V];
#pragma unroll
    for (int v = 0; v < V; v++) acc[v] = 0.f;

    if (valid) {
        float c = g_dinv2[node];
#pragma unroll
        for (int v = 0; v < V; v++) {
            float h = H[(size_t)node * F + col + v];
            float z = (LAYER > 0) ? fmaxf(fmaf(h, sc[v], sh[v]), 0.f) : h;
            acc[v] = z * c;
        }
        int beg = g_rowstart[node], end = g_rowstart[node + 1];
        for (int i = beg; i < end; i++) {
            int   s = g_csr_src[i];
            float c2 = g_csr_coef[i];
#pragma unroll
            for (int v = 0; v < V; v++) {
                float h = H[(size_t)s * F + col + v];
                float z = (LAYER > 0) ? fmaxf(fmaf(h, sc[v], sh[v]), 0.f) : h;
                acc[v] = fmaf(z, c2, acc[v]);
            }
        }
        if (OUTB) {
            if (V == 1) {
                __nv_bfloat16 h = __float2bfloat16(acc[0]);
                __nv_bfloat16 l = __float2bfloat16(acc[0] - __bfloat162float(h));
                AGGh[(size_t)node * F + col] = h;
                AGGl[(size_t)node * F + col] = l;
            } else {
                __nv_bfloat162 hp = __float22bfloat162_rn(make_float2(acc[0], acc[1]));
                __nv_bfloat162 lp = __float22bfloat162_rn(make_float2(
                    acc[0] - __bfloat162float(hp.x), acc[1] - __bfloat162float(hp.y)));
                *reinterpret_cast<uint32_t*>(&AGGh[(size_t)node * F + col]) = *reinterpret_cast<uint32_t*>(&hp);
                *reinterpret_cast<uint32_t*>(&AGGl[(size_t)node * F + col]) = *reinterpret_cast<uint32_t*>(&lp);
            }
        } else {
#pragma unroll
            for (int v = 0; v < V; v++) AGG[(size_t)node * F + col + v] = acc[v];
        }
    }

    if (STAT) {   // F == 32, V == 1
        ssum[wid * 32 + lane] = valid ? acc[0] : 0.f;
        ssq[wid * 32 + lane]  = valid ? acc[0] * acc[0] : 0.f;
        __syncthreads();
        if (wid == 0) {
            float s = 0.f, q = 0.f;
#pragma unroll
            for (int t = 0; t < 8; t++) { s += ssum[t * 32 + lane]; q += ssq[t * 32 + lane]; }
            atomicAdd(&g_sum1[lane], s);
            atomicAdd(&g_sq1[lane], q);
        }
        __threadfence();
        __syncthreads();
        if (threadIdx.x == 0)
            lastflag = (atomicAdd(&g_tick[0], 1) == (int)gridDim.x - 1) ? 1 : 0;
        __syncthreads();
        if (lastflag && threadIdx.x < 32) {
            int i = threadIdx.x;
            float mean = g_sum1[i] * (1.0f / NN);
            float var  = g_sq1[i] * (1.0f / NN) - mean * mean;
            float scv  = bng[i] * rsqrtf(var + 1e-5f);
            g_scale1[i] = scv;
            g_shift1[i] = bnbe[i] - mean * scv;
        }
    }
}

// ---------------- launch ----------------
extern "C" void kernel_launch(void* const* d_in, const int* in_sizes, int n_in,
                              void* d_out, int out_size) {
    (void)in_sizes; (void)n_in; (void)out_size;
    const float* x   = (const float*)d_in[0];
    const int*   eiw = (const int*)d_in[1];
    const float* W1  = (const float*)d_in[2];
    const float* W2  = (const float*)d_in[4];
    const float* W3  = (const float*)d_in[6];
    const float* g1  = (const float*)d_in[8];  const float* be1 = (const float*)d_in[9];
    const float* g2  = (const float*)d_in[10]; const float* be2 = (const float*)d_in[11];
    const float* g3  = (const float*)d_in[12]; const float* be3 = (const float*)d_in[13];
    const float* Wf1 = (const float*)d_in[14]; const float* bf1 = (const float*)d_in[15];
    const float* Wf2 = (const float*)d_in[16]; const float* bf2 = (const float*)d_in[17];
    const float* Wf3 = (const float*)d_in[18]; const float* bf3 = (const float*)d_in[19];
    const float* Wf4 = (const float*)d_in[20]; const float* bf4 = (const float*)d_in[21];
    float* out = (float*)d_out;

    const int RB = (NN + 127) / 128;     // 391
    const int GB = (NN + 7) / 8;         // 6250

    cudaFuncSetAttribute(k_gemm_mma<32, 0, 0, 0>,          cudaFuncAttributeMaxDynamicSharedMemorySize, mma_smem(32));
    cudaFuncSetAttribute(k_gemm_mma<64, 0, 0, 2, 0, 1>,    cudaFuncAttributeMaxDynamicSharedMemorySize, mma_smem(64));
    cudaFuncSetAttribute(k_gemm_mma<128, 0, 0, 3, 0, 1>,   cudaFuncAttributeMaxDynamicSharedMemorySize, mma_smem(128));
    cudaFuncSetAttribute(k_gemm_mma<128, 2, 3, 0, 0, 0, 1>, cudaFuncAttributeMaxDynamicSharedMemorySize, mma_smem(128));
    cudaFuncSetAttribute(k_gemm_mma<128, 2, 0, 0, 0, 1, 1>, cudaFuncAttributeMaxDynamicSharedMemorySize, mma_smem(128));
    cudaFuncSetAttribute(k_gemm_mma<64, 2, 0, 0, 1, 1, 0>,  cudaFuncAttributeMaxDynamicSharedMemorySize, mma_smem_outf());

    // fp32 ids: 0 h1, 1 agg1, 3 h2, 5 h3 | bf16-pair ids: 2 agg2, 4 agg3, 6 m1, 7 m2
    // wslots: 0=W3, 1=Wf1, 2=Wf2, 3=Wf3, 4=W1, 5=W2

    k_init<<<SBLKS, 256>>>(eiw);
    k_prepw_all<<<(88064 + 255) / 256, 256>>>(W3, Wf1, Wf2, Wf3, W1, W2);
    k_convert<<<(NE + 255) / 256, 256>>>(eiw);
    k_partsum<<<SBLKS, SCHUNK>>>();
    k_rowstart<<<SBLKS, SCHUNK>>>();
    k_gemm_mma<32, 0, 0, 0><<<dim3(RB, 1), 64, mma_smem(32)>>>(x, -1, 4, nullptr, nullptr, nullptr, nullptr, 0, NN, 128, 32);
    k_fill<<<(NE + 255) / 256, 256>>>();

    // layer 1: gather h1 -> agg1 (fp32), fused bn1 stats+final
    k_gather<32, 0, 1, 0><<<GB, 256>>>(0, 1, g1, be1);

    // layer 2: gather (applies bn1) -> agg2 bf16 pair; GEMM 32->64 (APRE) with fused bn2
    k_gather<32, 1, 0, 1><<<GB, 256>>>(1, 2, nullptr, nullptr);
    k_gemm_mma<64, 0, 0, 2, 0, 1><<<dim3(RB, 1), 128, mma_smem(64)>>>(nullptr, 2, 5, nullptr, g2, be2, nullptr, 3, NN, 32, 64);

    // layer 3: gather (applies bn2) -> agg3 bf16 pair; GEMM 64->128 (APRE) with fused bn3
    k_gather<64, 2, 0, 1><<<GB, 256>>>(3, 4, nullptr, nullptr);
    k_gemm_mma<128, 0, 0, 3, 0, 1><<<dim3(RB, 1), 256, mma_smem(128)>>>(nullptr, 4, 0, nullptr, g3, be3, nullptr, 5, NN, 64, 128);

    // MLP head: MLP1 (bn3+relu fused A-load) -> m1 bf16 pair
    k_gemm_mma<128, 2, 3, 0, 0, 0, 1><<<dim3(RB, 2), 256, mma_smem(128)>>>(nullptr, 5, 1, bf1, nullptr, nullptr, nullptr, 6, NN, 128, 256);
    // MLP2 (APRE) -> m2 bf16 pair
    k_gemm_mma<128, 2, 0, 0, 0, 1, 1><<<dim3(RB, 1), 256, mma_smem(128)>>>(nullptr, 6, 2, bf2, nullptr, nullptr, nullptr, 7, NN, 256, 128);
    // MLP3 (APRE) + fused final 64->10 fp32 GEMM writing d_out
    k_gemm_mma<64, 2, 0, 0, 1, 1, 0><<<dim3(RB, 1), 128, mma_smem_outf()>>>(nullptr, 7, 3, bf3, Wf4, bf4, out, -1, NN, 128, 64);
}

// round 16
// speedup vs baseline: 1.0630x; 1.0630x over previous
// AdvancedGCN kernel — build r15a (content-hash-breaking resubmit of r14)
#include <cuda_runtime.h>
#include <cuda_bf16.h>
#include <cstdint>

#define NN 50000
#define NE 800000
#define SCHUNK 256
#define SBLKS ((NN + SCHUNK - 1) / SCHUNK)   // 196

// ---------------- scratch ----------------
__device__ int   g_is64;
__device__ int   g_src[NE];
__device__ int   g_dst[NE];
__device__ int   g_cnt[NN];
__device__ int   g_fill[NN];
__device__ int   g_bsum[SBLKS];
__device__ int   g_boff[SBLKS];
__device__ int   g_rowstart[NN + 1];
__device__ int   g_csr_src[NE];
__device__ float g_csr_coef[NE];
__device__ float g_dinv[NN];
__device__ float g_dinv2[NN];
__device__ int   g_tick[4];

__device__ float g_h1[NN * 32];     // id 0
__device__ float g_agg1[NN * 32];   // id 1
__device__ float g_agg2[NN * 32];   // id 2
__device__ float g_h2[NN * 64];     // id 3
__device__ float g_agg3[NN * 64];   // id 4
__device__ float g_h3[NN * 128];    // id 5
__device__ float g_m1[NN * 256];    // id 6
__device__ float g_m2[NN * 128];    // id 7

// pre-split transposed weights, bf16 hi/lo, layout [F][K]
// slots: 0=W3(64x128) 1=Wf1(128x256) 2=Wf2(256x128) 3=Wf3(128x64) 4=W1(128x32) 5=W2(32x64)
__device__ __nv_bfloat16 g_wt_hi[6][32768];
__device__ __nv_bfloat16 g_wt_lo[6][32768];

__device__ float g_sum1[32],  g_sq1[32];
__device__ float g_sum2[64],  g_sq2[64];
__device__ float g_sum3[128], g_sq3[128];
__device__ float g_scale1[32],  g_shift1[32];
__device__ float g_scale2[64],  g_shift2[64];
__device__ float g_scale3[128], g_shift3[128];

__device__ __forceinline__ float* dev_buf(int id) {
    switch (id) {
        case 0:  return g_h1;
        case 1:  return g_agg1;
        case 2:  return g_agg2;
        case 3:  return g_h2;
        case 4:  return g_agg3;
        case 5:  return g_h3;
        case 6:  return g_m1;
        default: return g_m2;
    }
}

// ---------------- init (+parallel dtype detect in block 0) ----------------
__global__ void k_init(const int* __restrict__ w) {
    int i = blockIdx.x * blockDim.x + threadIdx.x;
    if (i < NN) { g_cnt[i] = 0; g_fill[i] = 0; }
    if (i < 128) { g_sum3[i] = 0.f; g_sq3[i] = 0.f; }
    if (i < 64)  { g_sum2[i] = 0.f; g_sq2[i] = 0.f; }
    if (i < 32)  { g_sum1[i] = 0.f; g_sq1[i] = 0.f; }
    if (i < 4)   g_tick[i] = 0;
    if (blockIdx.x == 0) {
        __shared__ int ok;
        if (threadIdx.x == 0) ok = 1;
        __syncthreads();
        if (threadIdx.x < 128) {
            int lo = w[2 * threadIdx.x], hi = w[2 * threadIdx.x + 1];
            if (hi != 0 || lo < 0 || lo >= NN) ok = 0;
        }
        __syncthreads();
        if (threadIdx.x == 0) g_is64 = ok;
    }
}

__global__ void k_convert(const int* __restrict__ w) {
    int e = blockIdx.x * blockDim.x + threadIdx.x;
    if (e >= NE) return;
    int s, d;
    if (g_is64) { s = w[2 * e]; d = w[2 * (NE + e)]; }
    else        { s = w[e];     d = w[NE + e]; }
    s = min(max(s, 0), NN - 1);
    d = min(max(d, 0), NN - 1);
    g_src[e] = s;
    g_dst[e] = d;
    atomicAdd(&g_cnt[d], 1);
}

// ---------- scan: partial sums (+ fused scan of partials in last block) ----------
__global__ __launch_bounds__(SCHUNK) void k_partsum() {
    __shared__ int sh[SCHUNK];
    __shared__ int lastflag;
    int idx = blockIdx.x * SCHUNK + threadIdx.x;
    int v = (idx < NN) ? g_cnt[idx] : 0;
    sh[threadIdx.x] = v;
    __syncthreads();
    for (int off = SCHUNK / 2; off > 0; off >>= 1) {
        if (threadIdx.x < off) sh[threadIdx.x] += sh[threadIdx.x + off];
        __syncthreads();
    }
    if (threadIdx.x == 0) g_bsum[blockIdx.x] = sh[0];
    __threadfence();
    __syncthreads();
    if (threadIdx.x == 0)
        lastflag = (atomicAdd(&g_tick[3], 1) == (int)gridDim.x - 1) ? 1 : 0;
    __syncthreads();
    if (lastflag) {
        int t = threadIdx.x;
        int u = (t < SBLKS) ? g_bsum[t] : 0;
        sh[t] = u;
        __syncthreads();
        for (int off = 1; off < SCHUNK; off <<= 1) {
            int w = (t >= off) ? sh[t - off] : 0;
            __syncthreads();
            sh[t] += w;
            __syncthreads();
        }
        if (t < SBLKS) g_boff[t] = sh[t] - u;   // exclusive
    }
}

__global__ __launch_bounds__(SCHUNK) void k_rowstart() {
    __shared__ int sh[SCHUNK];
    int idx = blockIdx.x * SCHUNK + threadIdx.x;
    int c = (idx < NN) ? g_cnt[idx] : 0;
    sh[threadIdx.x] = c;
    __syncthreads();
    for (int off = 1; off < SCHUNK; off <<= 1) {
        int u = (threadIdx.x >= off) ? sh[threadIdx.x - off] : 0;
        __syncthreads();
        sh[threadIdx.x] += u;
        __syncthreads();
    }
    if (idx < NN) {
        int rs = g_boff[blockIdx.x] + sh[threadIdx.x] - c;
        g_rowstart[idx] = rs;
        float r = rsqrtf((float)(c + 1));
        g_dinv[idx]  = r;
        g_dinv2[idx] = r * r;
        if (idx == NN - 1) g_rowstart[NN] = rs + c;
    }
}

__global__ void k_fill() {
    int e = blockIdx.x * blockDim.x + threadIdx.x;
    if (e >= NE) return;
    int s = g_src[e], d = g_dst[e];
    int pos = g_rowstart[d] + atomicAdd(&g_fill[d], 1);
    g_csr_src[pos]  = s;
    g_csr_coef[pos] = g_dinv[s] * g_dinv[d];
}

// ---------------- weight prep (all 6 slots fused): W[K][F] fp32 -> [F][K] bf16 hi/lo ----
__global__ void k_prepw_all(const float* __restrict__ w0, const float* __restrict__ w1,
                            const float* __restrict__ w2, const float* __restrict__ w3,
                            const float* __restrict__ w4, const float* __restrict__ w5) {
    int idx = blockIdx.x * blockDim.x + threadIdx.x;
    if (idx >= 88064) return;
    int slot, base, K;
    const float* W;
    if      (idx < 8192)  { slot = 0; base = 0;     K = 64;  W = w0; }
    else if (idx < 40960) { slot = 1; base = 8192;  K = 128; W = w1; }
    else if (idx < 73728) { slot = 2; base = 40960; K = 256; W = w2; }
    else if (idx < 81920) { slot = 3; base = 73728; K = 128; W = w3; }
    else if (idx < 86016) { slot = 4; base = 81920; K = 128; W = w4; }
    else                  { slot = 5; base = 86016; K = 32;  W = w5; }
    int li = idx - base;
    int sz = (slot == 0 || slot == 3) ? 8192 : (slot == 1 || slot == 2) ? 32768 :
             (slot == 4) ? 4096 : 2048;
    int F = sz / K;
    int f = li / K, k = li % K;
    float v = W[(size_t)k * F + f];
    __nv_bfloat16 h = __float2bfloat16(v);
    __nv_bfloat16 l = __float2bfloat16(v - __bfloat162float(h));
    g_wt_hi[slot][li] = h;
    g_wt_lo[slot][li] = l;
}

// ---------------- HMMA bf16 split GEMM ----------------
#define MMA_BF16(d, a, b)                                                       \
    asm volatile("mma.sync.aligned.m16n8k16.row.col.f32.bf16.bf16.f32 "         \
        "{%0,%1,%2,%3}, {%4,%5,%6,%7}, {%8,%9}, {%0,%1,%2,%3};"                 \
        : "+f"(d[0]), "+f"(d[1]), "+f"(d[2]), "+f"(d[3])                        \
        : "r"(a[0]), "r"(a[1]), "r"(a[2]), "r"(a[3]), "r"(b[0]), "r"(b[1]))

// STATL: 0 none; 2/3 = fused BN stats of output. OUTF: 1 = fused final 64->10 GEMM
template <int BN, int EPI, int LAYERA, int STATL, int OUTF = 0>
__global__ __launch_bounds__(2 * (BN / 32) * 32)
void k_gemm_mma(const float* __restrict__ Aext, int aId, int wslot,
                const float* __restrict__ bias,
                const float* __restrict__ bng, const float* __restrict__ bnbe,
                float* __restrict__ Cext, int cId, int nrows, int K, int F) {
    constexpr int BM = 128, WN = BN / 32, THREADS = 2 * WN * 32;
    constexpr int AS = 40;
    constexpr int ASZ = BM * AS, BSZ = BN * AS;
    extern __shared__ __nv_bfloat16 dsm[];
    __shared__ int lastflag;

    const float* A = Aext ? Aext : dev_buf(aId);
    float* C = Cext ? Cext : dev_buf(cId);
    const __nv_bfloat16* __restrict__ Wh = g_wt_hi[wslot];
    const __nv_bfloat16* __restrict__ Wl = g_wt_lo[wslot];

    int tid = threadIdx.x, wid = tid >> 5, lane = tid & 31;
    int warpM = wid / WN, warpN = wid % WN;
    int grp = lane >> 2, tig = lane & 3;
    int row0 = blockIdx.x * BM, c0 = blockIdx.y * BN;

    float acc[4][4][4];
#pragma unroll
    for (int mt = 0; mt < 4; mt++)
#pragma unroll
        for (int nt = 0; nt < 4; nt++)
#pragma unroll
            for (int q = 0; q < 4; q++) acc[mt][nt][q] = 0.f;

    __nv_bfloat16* Ah = dsm;
    __nv_bfloat16* Al = Ah + ASZ;
    __nv_bfloat16* Bh = Al + ASZ;
    __nv_bfloat16* Bl = Bh + BSZ;

    for (int k0 = 0; k0 < K; k0 += 32) {
        for (int u = tid; u < BM * 2; u += THREADS) {
            int r = u >> 1, h = (u & 1) * 16;
            float vv[16];
            if (row0 + r < nrows) {
#pragma unroll
                for (int q = 0; q < 4; q++) {
                    float4 v = *reinterpret_cast<const float4*>(
                        &A[(size_t)(row0 + r) * K + k0 + h + q * 4]);
                    vv[q * 4] = v.x; vv[q * 4 + 1] = v.y; vv[q * 4 + 2] = v.z; vv[q * 4 + 3] = v.w;
                }
            } else {
#pragma unroll
                for (int q = 0; q < 16; q++) vv[q] = 0.f;
            }
            if (LAYERA == 3) {
#pragma unroll
                for (int q = 0; q < 16; q++)
                    vv[q] = fmaxf(fmaf(vv[q], g_scale3[k0 + h + q], g_shift3[k0 + h + q]), 0.f);
            }
#pragma unroll
            for (int q = 0; q < 16; q += 2) {
                __nv_bfloat162 hp = __float22bfloat162_rn(make_float2(vv[q], vv[q + 1]));
                float l0 = vv[q]     - __bfloat162float(hp.x);
                float l1 = vv[q + 1] - __bfloat162float(hp.y);
                __nv_bfloat162 lp = __float22bfloat162_rn(make_float2(l0, l1));
                *reinterpret_cast<uint32_t*>(&Ah[r * AS + h + q]) = *reinterpret_cast<uint32_t*>(&hp);
                *reinterpret_cast<uint32_t*>(&Al[r * AS + h + q]) = *reinterpret_cast<uint32_t*>(&lp);
            }
        }
        for (int u = tid; u < BN * 8; u += THREADS) {
            int n = u >> 3, q = (u & 7) * 4;
            uint2 vh = *reinterpret_cast<const uint2*>(&Wh[(size_t)(c0 + n) * K + k0 + q]);
            uint2 vl = *reinterpret_cast<const uint2*>(&Wl[(size_t)(c0 + n) * K + k0 + q]);
            *reinterpret_cast<uint2*>(&Bh[n * AS + q]) = vh;
            *reinterpret_cast<uint2*>(&Bl[n * AS + q]) = vl;
        }
        __syncthreads();

#pragma unroll
        for (int ks = 0; ks < 32; ks += 16) {
            uint32_t bhf[4][2], blf[4][2];
#pragma unroll
            for (int nt = 0; nt < 4; nt++) {
                int n = warpN * 32 + nt * 8 + grp;
                bhf[nt][0] = *reinterpret_cast<const uint32_t*>(&Bh[n * AS + ks + tig * 2]);
                bhf[nt][1] = *reinterpret_cast<const uint32_t*>(&Bh[n * AS + ks + tig * 2 + 8]);
                blf[nt][0] = *reinterpret_cast<const uint32_t*>(&Bl[n * AS + ks + tig * 2]);
                blf[nt][1] = *reinterpret_cast<const uint32_t*>(&Bl[n * AS + ks + tig * 2 + 8]);
            }
#pragma unroll
            for (int mt = 0; mt < 4; mt++) {
                int r0 = warpM * 64 + mt * 16 + grp;
                uint32_t ahf[4], alf[4];
                ahf[0] = *reinterpret_cast<const uint32_t*>(&Ah[r0 * AS + ks + tig * 2]);
                ahf[1] = *reinterpret_cast<const uint32_t*>(&Ah[(r0 + 8) * AS + ks + tig * 2]);
                ahf[2] = *reinterpret_cast<const uint32_t*>(&Ah[r0 * AS + ks + tig * 2 + 8]);
                ahf[3] = *reinterpret_cast<const uint32_t*>(&Ah[(r0 + 8) * AS + ks + tig * 2 + 8]);
                alf[0] = *reinterpret_cast<const uint32_t*>(&Al[r0 * AS + ks + tig * 2]);
                alf[1] = *reinterpret_cast<const uint32_t*>(&Al[(r0 + 8) * AS + ks + tig * 2]);
                alf[2] = *reinterpret_cast<const uint32_t*>(&Al[r0 * AS + ks + tig * 2 + 8]);
                alf[3] = *reinterpret_cast<const uint32_t*>(&Al[(r0 + 8) * AS + ks + tig * 2 + 8]);
#pragma unroll
                for (int nt = 0; nt < 4; nt++) {
                    MMA_BF16(acc[mt][nt], ahf, bhf[nt]);
                    MMA_BF16(acc[mt][nt], ahf, blf[nt]);
                    MMA_BF16(acc[mt][nt], alf, bhf[nt]);
                }
            }
        }
        __syncthreads();
    }

    // ---- epilogue ----
    float* stage = reinterpret_cast<float*>(dsm);   // OUTF staging (stride 65)
    float ls[4][2], lq[4][2];
    if (STATL) {
#pragma unroll
        for (int nt = 0; nt < 4; nt++) { ls[nt][0] = ls[nt][1] = lq[nt][0] = lq[nt][1] = 0.f; }
    }
#pragma unroll
    for (int mt = 0; mt < 4; mt++) {
#pragma unroll
        for (int nt = 0; nt < 4; nt++) {
            int rl = warpM * 64 + mt * 16 + grp;
            int row = row0 + rl;
            int col = c0 + warpN * 32 + nt * 8 + tig * 2;
            float2 v0 = make_float2(acc[mt][nt][0], acc[mt][nt][1]);
            float2 v1 = make_float2(acc[mt][nt][2], acc[mt][nt][3]);
            if (EPI == 2) {
                float b0 = bias[col], b1 = bias[col + 1];
                v0.x = fmaxf(v0.x + b0, 0.f); v0.y = fmaxf(v0.y + b1, 0.f);
                v1.x = fmaxf(v1.x + b0, 0.f); v1.y = fmaxf(v1.y + b1, 0.f);
            }
            if (STATL) {   // out-of-range rows produce exact zeros (zero-filled A)
                ls[nt][0] += v0.x + v1.x;
                ls[nt][1] += v0.y + v1.y;
                lq[nt][0] += v0.x * v0.x + v1.x * v1.x;
                lq[nt][1] += v0.y * v0.y + v1.y * v1.y;
            }
            if (OUTF) {
                stage[rl * 65 + col]       = v0.x;
                stage[rl * 65 + col + 1]   = v0.y;
                stage[(rl + 8) * 65 + col]     = v1.x;
                stage[(rl + 8) * 65 + col + 1] = v1.y;
            } else {
                if (row < nrows)
                    *reinterpret_cast<float2*>(&C[(size_t)row * F + col]) = v0;
                if (row + 8 < nrows)
                    *reinterpret_cast<float2*>(&C[(size_t)(row + 8) * F + col]) = v1;
            }
        }
    }

    if (OUTF) {   // fused 64->10 fp32 GEMM: out = stage @ W4 + b4  (W4 in bng, b4 in bnbe)
        float* w4s = stage + 128 * 65;   // 640 floats
        for (int i = tid; i < 640; i += THREADS) w4s[i] = bng[i];
        __syncthreads();
        int row = row0 + tid;
        if (tid < 128 && row < nrows) {
            float o[10];
#pragma unroll
            for (int c = 0; c < 10; c++) o[c] = bnbe[c];
            for (int k = 0; k < 64; k++) {
                float a = stage[tid * 65 + k];
#pragma unroll
                for (int c = 0; c < 10; c++) o[c] = fmaf(a, w4s[k * 10 + c], o[c]);
            }
#pragma unroll
            for (int c = 0; c < 10; c++) C[(size_t)row * 10 + c] = o[c];
        }
    }

    if (STATL) {
        float* sum = (STATL == 2) ? g_sum2 : g_sum3;
        float* sq  = (STATL == 2) ? g_sq2  : g_sq3;
        float* scale = (STATL == 2) ? g_scale2 : g_scale3;
        float* shift = (STATL == 2) ? g_shift2 : g_shift3;
#pragma unroll
        for (int nt = 0; nt < 4; nt++) {
#pragma unroll
            for (int c = 0; c < 2; c++) {
                float s = ls[nt][c], q = lq[nt][c];
#pragma unroll
                for (int off = 4; off < 32; off <<= 1) {
                    s += __shfl_xor_sync(0xFFFFFFFFu, s, off);
                    q += __shfl_xor_sync(0xFFFFFFFFu, q, off);
                }
                if (lane < 4) {
                    int col = c0 + warpN * 32 + nt * 8 + lane * 2 + c;
                    atomicAdd(&sum[col], s);
                    atomicAdd(&sq[col], q);
                }
            }
        }
        __threadfence();
        __syncthreads();
        if (tid == 0)
            lastflag = (atomicAdd(&g_tick[STATL - 1], 1) ==
                        (int)(gridDim.x * gridDim.y) - 1) ? 1 : 0;
        __syncthreads();
        if (lastflag && tid < F) {
            float mean = sum[tid] * (1.0f / NN);
            float var  = sq[tid] * (1.0f / NN) - mean * mean;
            float scv  = bng[tid] * rsqrtf(var + 1e-5f);
            scale[tid] = scv;
            shift[tid] = bnbe[tid] - mean * scv;
        }
    }
}

// dynamic smem bytes (single buffer); OUTF needs staging room
constexpr int mma_smem(int BN) { return (2 * 128 * 40 + 2 * BN * 40) * 2; }
constexpr int mma_smem_outf()  { return (128 * 65 + 640) * 4; }   // 35840 > mma_smem(64)

// ---------------- CSR gather (+ optional fused BN1 stats for STAT=1, F=32) ----------
template <int F, int LAYER, int STAT>
__launch_bounds__(256)
__global__ void k_gather(int hId, int aggId,
                         const float* __restrict__ bng, const float* __restrict__ bnbe) {
    const float* __restrict__ H = dev_buf(hId);
    float* __restrict__ AGG = dev_buf(aggId);
    constexpr int V = F / 32;
    __shared__ float ssum[8 * 32], ssq[8 * 32];
    __shared__ int lastflag;
    int wid = threadIdx.x >> 5;
    int node = blockIdx.x * 8 + wid;
    int lane = threadIdx.x & 31;
    int col = lane * V;
    bool valid = node < NN;

    float sc[V], sh[V];
    if (LAYER > 0) {
        const float* scale = (LAYER == 1) ? g_scale1 : g_scale2;
        const float* shift = (LAYER == 1) ? g_shift1 : g_shift2;
#pragma unroll
        for (int v = 0; v < V; v++) { sc[v] = scale[col + v]; sh[v] = shift[col + v]; }
    }

    float acc[V];
#pragma unroll
    for (int v = 0; v < V; v++) acc[v] = 0.f;

    if (valid) {
        float c = g_dinv2[node];
#pragma unroll
        for (int v = 0; v < V; v++) {
            float h = H[(size_t)node * F + col + v];
            float z = (LAYER > 0) ? fmaxf(fmaf(h, sc[v], sh[v]), 0.f) : h;
            acc[v] = z * c;
        }
        int beg = g_rowstart[node], end = g_rowstart[node + 1];
        for (int i = beg; i < end; i++) {
            int   s = g_csr_src[i];
            float c2 = g_csr_coef[i];
#pragma unroll
            for (int v = 0; v < V; v++) {
                float h = H[(size_t)s * F + col + v];
                float z = (LAYER > 0) ? fmaxf(fmaf(h, sc[v], sh[v]), 0.f) : h;
                acc[v] = fmaf(z, c2, acc[v]);
            }
        }
#pragma unroll
        for (int v = 0; v < V; v++) AGG[(size_t)node * F + col + v] = acc[v];
    }

    if (STAT) {   // F == 32, V == 1
        ssum[wid * 32 + lane] = valid ? acc[0] : 0.f;
        ssq[wid * 32 + lane]  = valid ? acc[0] * acc[0] : 0.f;
        __syncthreads();
        if (wid == 0) {
            float s = 0.f, q = 0.f;
#pragma unroll
            for (int t = 0; t < 8; t++) { s += ssum[t * 32 + lane]; q += ssq[t * 32 + lane]; }
            atomicAdd(&g_sum1[lane], s);
            atomicAdd(&g_sq1[lane], q);
        }
        __threadfence();
        __syncthreads();
        if (threadIdx.x == 0)
            lastflag = (atomicAdd(&g_tick[0], 1) == (int)gridDim.x - 1) ? 1 : 0;
        __syncthreads();
        if (lastflag && threadIdx.x < 32) {
            int i = threadIdx.x;
            float mean = g_sum1[i] * (1.0f / NN);
            float var  = g_sq1[i] * (1.0f / NN) - mean * mean;
            float scv  = bng[i] * rsqrtf(var + 1e-5f);
            g_scale1[i] = scv;
            g_shift1[i] = bnbe[i] - mean * scv;
        }
    }
}

// ---------------- launch ----------------
extern "C" void kernel_launch(void* const* d_in, const int* in_sizes, int n_in,
                              void* d_out, int out_size) {
    (void)in_sizes; (void)n_in; (void)out_size;
    const float* x   = (const float*)d_in[0];
    const int*   eiw = (const int*)d_in[1];
    const float* W1  = (const float*)d_in[2];
    const float* W2  = (const float*)d_in[4];
    const float* W3  = (const float*)d_in[6];
    const float* g1  = (const float*)d_in[8];  const float* be1 = (const float*)d_in[9];
    const float* g2  = (const float*)d_in[10]; const float* be2 = (const float*)d_in[11];
    const float* g3  = (const float*)d_in[12]; const float* be3 = (const float*)d_in[13];
    const float* Wf1 = (const float*)d_in[14]; const float* bf1 = (const float*)d_in[15];
    const float* Wf2 = (const float*)d_in[16]; const float* bf2 = (const float*)d_in[17];
    const float* Wf3 = (const float*)d_in[18]; const float* bf3 = (const float*)d_in[19];
    const float* Wf4 = (const float*)d_in[20]; const float* bf4 = (const float*)d_in[21];
    float* out = (float*)d_out;

    const int RB = (NN + 127) / 128;     // 391
    const int GB = (NN + 7) / 8;         // 6250

    cudaFuncSetAttribute(k_gemm_mma<32, 0, 0, 0>,     cudaFuncAttributeMaxDynamicSharedMemorySize, mma_smem(32));
    cudaFuncSetAttribute(k_gemm_mma<64, 0, 0, 2>,     cudaFuncAttributeMaxDynamicSharedMemorySize, mma_smem(64));
    cudaFuncSetAttribute(k_gemm_mma<128, 0, 0, 3>,    cudaFuncAttributeMaxDynamicSharedMemorySize, mma_smem(128));
    cudaFuncSetAttribute(k_gemm_mma<128, 2, 3, 0>,    cudaFuncAttributeMaxDynamicSharedMemorySize, mma_smem(128));
    cudaFuncSetAttribute(k_gemm_mma<128, 2, 0, 0>,    cudaFuncAttributeMaxDynamicSharedMemorySize, mma_smem(128));
    cudaFuncSetAttribute(k_gemm_mma<64, 2, 0, 0, 1>,  cudaFuncAttributeMaxDynamicSharedMemorySize, mma_smem_outf());

    // ids: 0 h1, 1 agg1, 2 agg2, 3 h2, 4 agg3, 5 h3, 6 m1, 7 m2
    // wslots: 0=W3, 1=Wf1, 2=Wf2, 3=Wf3, 4=W1, 5=W2

    k_init<<<SBLKS, 256>>>(eiw);
    k_prepw_all<<<(88064 + 255) / 256, 256>>>(W3, Wf1, Wf2, Wf3, W1, W2);
    k_convert<<<(NE + 255) / 256, 256>>>(eiw);
    k_partsum<<<SBLKS, SCHUNK>>>();
    k_rowstart<<<SBLKS, SCHUNK>>>();
    k_gemm_mma<32, 0, 0, 0><<<dim3(RB, 1), 64, mma_smem(32)>>>(x, -1, 4, nullptr, nullptr, nullptr, nullptr, 0, NN, 128, 32);
    k_fill<<<(NE + 255) / 256, 256>>>();

    // layer 1: gather h1 -> agg1, fused bn1 stats+final
    k_gather<32, 0, 1><<<GB, 256>>>(0, 1, g1, be1);

    // layer 2: gather (applies bn1) -> agg2; GEMM 32->64 with fused bn2
    k_gather<32, 1, 0><<<GB, 256>>>(1, 2, nullptr, nullptr);
    k_gemm_mma<64, 0, 0, 2><<<dim3(RB, 1), 128, mma_smem(64)>>>(nullptr, 2, 5, nullptr, g2, be2, nullptr, 3, NN, 32, 64);

    // layer 3: gather (applies bn2) -> agg3; GEMM 64->128 with fused bn3
    k_gather<64, 2, 0><<<GB, 256>>>(3, 4, nullptr, nullptr);
    k_gemm_mma<128, 0, 0, 3><<<dim3(RB, 1), 256, mma_smem(128)>>>(nullptr, 4, 0, nullptr, g3, be3, nullptr, 5, NN, 64, 128);

    // MLP head: MLP1 BN=128 x 2 y-blocks (bn3+relu fused into A-load)
    k_gemm_mma<128, 2, 3, 0><<<dim3(RB, 2), 256, mma_smem(128)>>>(nullptr, 5, 1, bf1, nullptr, nullptr, nullptr, 6, NN, 128, 256);
    k_gemm_mma<128, 2, 0, 0><<<dim3(RB, 1), 256, mma_smem(128)>>>(nullptr, 6, 2, bf2, nullptr, nullptr, nullptr, 7, NN, 256, 128);
    // MLP3 64-out with fused final 64->10 fp32 GEMM writing d_out directly
    k_gemm_mma<64, 2, 0, 0, 1><<<dim3(RB, 1), 128, mma_smem_outf()>>>(nullptr, 7, 3, bf3, Wf4, bf4, out, -1, NN, 128, 64);
}